// round 13
// baseline (speedup 1.0000x reference)
#include <cuda_runtime.h>
#include <cuda_bf16.h>

// Problem shape (fixed by the reference)
#define BB 16
#define TT 4096
#define HH 512
#define H4 (HH / 4)      // 128 float4 per row
#define JC 64            // chunks (CTAs) per batch; row stride = JC
#define ROWS (TT / JC)   // 64 interleaved rows per CTA
#define GRP 8            // chunks per reduction group
#define NG (JC / GRP)    // 8 groups per batch

// Scratch. All mutated state is reset by the finalizer -> graph-replayable.
__device__ float g_partial[BB][JC][2 * HH];   // 4 MiB, unique per CTA (plain STG)
__device__ int   g_cnt1[BB][JC];
__device__ float g_final[BB][2 * HH];         // 128 KB accumulated via REDG
__device__ int   g_cntf[BB];
__device__ int   g_gdone[BB][NG];
__device__ int   g_done[BB];

__global__ __launch_bounds__(128) void pool_kernel(
    const float4* __restrict__ x,
    const int* __restrict__ lengths,
    const int* __restrict__ mask,        // jax bool materialized as int32
    float* __restrict__ out)
{
    const int bid = blockIdx.x;          // 0..1023
    const int b   = bid & (BB - 1);      // batch cycles fastest -> SM mix
    const int j   = bid >> 4;            // 0..63, interleave offset
    const int tid = threadIdx.x;         // 0..127

    const int L = lengths[b];
    // rows t = j + JC*k ; count with t < L:
    int Lc = (L > j) ? ((L - j + JC - 1) >> 6) : 0;
    if (Lc > ROWS) Lc = ROWS;

    const float4* __restrict__ xp = x + (size_t)b * TT * H4 + (size_t)j * H4 + tid;
    const int* __restrict__ mp = mask + (size_t)b * TT + j;

    float4 ag = make_float4(0.f, 0.f, 0.f, 0.f);
    float4 al = make_float4(0.f, 0.f, 0.f, 0.f);
    int cnt = 0;

    // Region A: rows in the global view (always fetched); mask gates local.
    int k = 0;
    #pragma unroll 8
    for (; k < Lc; ++k) {
        float4 v = xp[(size_t)(k * JC) * H4];
        ag.x += v.x; ag.y += v.y; ag.z += v.z; ag.w += v.w;
        if (mp[k << 6] != 0) { al.x += v.x; al.y += v.y; al.z += v.z; al.w += v.w; cnt++; }
    }
    // Region B: fetch only masked rows (warp-uniform skip).
    #pragma unroll 4
    for (; k < ROWS; ++k) {
        if (mp[k << 6] != 0) {
            float4 v = xp[(size_t)(k * JC) * H4];
            al.x += v.x; al.y += v.y; al.z += v.z; al.w += v.w; cnt++;
        }
    }

    // Publish unique partial (plain stores).
    float4* outp = reinterpret_cast<float4*>(&g_partial[b][j][0]);
    outp[tid]       = ag;
    outp[H4 + tid]  = al;
    if (tid == 0) g_cnt1[b][j] = cnt;

    __shared__ int sv;
    __threadfence();
    __syncthreads();
    if (tid == 0) sv = atomicAdd(&g_gdone[b][j >> 3], 1);
    __syncthreads();
    if (sv != GRP - 1) return;

    // ---- 8th arriver of this group: reduce 8 partials (32 KB, L2-hot) ----
    __threadfence();
    const int j0 = (j >> 3) << 3;
    #pragma unroll
    for (int k2 = 0; k2 < 2; ++k2) {
        const int fc = k2 * 128 + tid;   // float4 column in [0, 256)
        float4 sum = make_float4(0.f, 0.f, 0.f, 0.f);
        #pragma unroll
        for (int c = 0; c < GRP; ++c) {
            float4 v = reinterpret_cast<float4*>(&g_partial[b][j0 + c][0])[fc];
            sum.x += v.x; sum.y += v.y; sum.z += v.z; sum.w += v.w;
        }
        float* gf = &g_final[b][0] + 4 * fc;
        atomicAdd(gf + 0, sum.x);
        atomicAdd(gf + 1, sum.y);
        atomicAdd(gf + 2, sum.z);
        atomicAdd(gf + 3, sum.w);
    }
    if (tid == 0) {
        int c8 = 0;
        #pragma unroll
        for (int c = 0; c < GRP; ++c) c8 += g_cnt1[b][j0 + c];
        atomicAdd(&g_cntf[b], c8);
    }

    __threadfence();
    __syncthreads();
    if (tid == 0) sv = atomicAdd(&g_done[b], 1);
    __syncthreads();
    if (sv != NG - 1) return;

    // ---- last group of this batch: finalize (4 KB, L2-hot) ----
    __threadfence();
    const int tot = g_cntf[b];
    const float dg = 1.0f / (float)(L   > 1 ? L   : 1);
    const float dl = 1.0f / (float)(tot > 1 ? tot : 1);

    float4* o4 = reinterpret_cast<float4*>(out) + (size_t)b * (2 * HH / 4);
    #pragma unroll
    for (int k2 = 0; k2 < 2; ++k2) {
        const int fc = k2 * 128 + tid;
        float4 s = reinterpret_cast<float4*>(&g_final[b][0])[fc];
        const float inv = (fc < H4) ? dg : dl;
        o4[fc] = make_float4(s.x * inv, s.y * inv, s.z * inv, s.w * inv);
        reinterpret_cast<float4*>(&g_final[b][0])[fc] =
            make_float4(0.f, 0.f, 0.f, 0.f);
    }
    if (tid == 0) { g_cntf[b] = 0; g_done[b] = 0; }
    if (tid < NG) g_gdone[b][tid] = 0;
}

extern "C" void kernel_launch(void* const* d_in, const int* in_sizes, int n_in,
                              void* d_out, int out_size)
{
    const float4* x       = (const float4*)d_in[0];   // [B,T,H] f32
    const int*    lengths = (const int*)d_in[1];      // [B] i32
    const int*    mask    = (const int*)d_in[2];      // [B,T] bool -> i32
    float*        out     = (float*)d_out;            // [B, 2H] f32

    pool_kernel<<<BB * JC, 128>>>(x, lengths, mask, out);
}

// round 14
// speedup vs baseline: 1.5838x; 1.5838x over previous
#include <cuda_runtime.h>
#include <cuda_bf16.h>

// Problem shape (fixed by the reference)
#define BB 16
#define TT 4096
#define HH 512
#define SS 64            // T-chunks per batch
#define TC (TT / SS)     // 64 rows per chunk
#define H4 (HH / 4)      // 128 float4 per row
#define CP 16            // pass-2 chunk-splits  (SS/CP = 4 chunks per thread)
#define COLP 2           // pass-2 column-splits (each CTA: 128 float4-cols)

// Scratch: per (b, chunk): 512 global-sum + 512 local-sum floats (4 MiB)
__device__ float g_partial[BB * SS * 2 * HH];
__device__ int   g_counts[BB * SS];

// Pass 1: each CTA handles one contiguous (b, t-chunk); 128 threads x float4.
// Region A is batched 4 rows deep with BRANCH-FREE fma accumulation so ptxas
// front-batches 4+ independent LDG.128 (deep MLP). Region B keeps the
// warp-uniform dead-row skip (~25% traffic cut). First 32 CTAs zero out[].
__global__ __launch_bounds__(128) void pass1_kernel(
    const float4* __restrict__ x,
    const int* __restrict__ lengths,
    const int* __restrict__ mask,        // jax bool materialized as int32
    float4* __restrict__ out4)           // [B*2H/4] — zeroed here
{
    const int blk = blockIdx.x;          // 0 .. B*SS-1
    const int b   = blk / SS;
    const int s   = blk % SS;
    const int tid = threadIdx.x;         // 0..127

    if (blk < 32) out4[blk * 128 + tid] = make_float4(0.f, 0.f, 0.f, 0.f);

    const int L  = lengths[b];
    const int t0 = s * TC;
    int Lc = L - t0;
    Lc = Lc < 0 ? 0 : (Lc > TC ? TC : Lc);

    const float4* __restrict__ xp = x + (size_t)b * TT * H4 + (size_t)t0 * H4 + tid;
    const int* __restrict__ mp = mask + (size_t)b * TT + t0;   // 256B-aligned

    float4 ag = make_float4(0.f, 0.f, 0.f, 0.f);
    float4 al = make_float4(0.f, 0.f, 0.f, 0.f);
    int cnt = 0;

    // ---- Region A: t < Lc. 4-row batches, branch-free accumulation. ----
    const int LcA = Lc & ~3;
    int t = 0;
    #pragma unroll 2
    for (; t < LcA; t += 4) {
        const float4 v0 = xp[(size_t)(t + 0) * H4];
        const float4 v1 = xp[(size_t)(t + 1) * H4];
        const float4 v2 = xp[(size_t)(t + 2) * H4];
        const float4 v3 = xp[(size_t)(t + 3) * H4];
        const int4 mm = *reinterpret_cast<const int4*>(mp + t);

        ag.x += (v0.x + v1.x) + (v2.x + v3.x);
        ag.y += (v0.y + v1.y) + (v2.y + v3.y);
        ag.z += (v0.z + v1.z) + (v2.z + v3.z);
        ag.w += (v0.w + v1.w) + (v2.w + v3.w);

        const float w0 = mm.x ? 1.f : 0.f;
        const float w1 = mm.y ? 1.f : 0.f;
        const float w2 = mm.z ? 1.f : 0.f;
        const float w3 = mm.w ? 1.f : 0.f;
        al.x = fmaf(w0, v0.x, fmaf(w1, v1.x, fmaf(w2, v2.x, fmaf(w3, v3.x, al.x))));
        al.y = fmaf(w0, v0.y, fmaf(w1, v1.y, fmaf(w2, v2.y, fmaf(w3, v3.y, al.y))));
        al.z = fmaf(w0, v0.z, fmaf(w1, v1.z, fmaf(w2, v2.z, fmaf(w3, v3.z, al.z))));
        al.w = fmaf(w0, v0.w, fmaf(w1, v1.w, fmaf(w2, v2.w, fmaf(w3, v3.w, al.w))));
        cnt += (mm.x ? 1 : 0) + (mm.y ? 1 : 0) + (mm.z ? 1 : 0) + (mm.w ? 1 : 0);
    }
    // Region-A remainder (0-3 rows).
    for (; t < Lc; ++t) {
        float4 v = xp[(size_t)t * H4];
        ag.x += v.x; ag.y += v.y; ag.z += v.z; ag.w += v.w;
        if (mp[t] != 0) { al.x += v.x; al.y += v.y; al.z += v.z; al.w += v.w; cnt++; }
    }
    // ---- Region B: t >= Lc — fetch only masked rows (uniform skip). ----
    #pragma unroll 4
    for (; t < TC; ++t) {
        if (mp[t] != 0) {
            float4 v = xp[(size_t)t * H4];
            al.x += v.x; al.y += v.y; al.z += v.z; al.w += v.w; cnt++;
        }
    }

    float4* outp = reinterpret_cast<float4*>(g_partial) + (size_t)blk * (2 * HH / 4);
    outp[tid]      = ag;
    outp[H4 + tid] = al;
    if (tid == 0) g_counts[blk] = cnt;
}

// Pass 2: 512 CTAs = (b, colpart, chunkpart); 128 threads. float4 partial
// loads (4 chunks/thread), per-CTA count reduce only for local-half CTAs,
// pre-divide, 4 scalar atomicAdds into out.
__global__ __launch_bounds__(128) void pass2_kernel(
    const int* __restrict__ lengths,
    float* __restrict__ out)
{
    const int blk       = blockIdx.x;
    const int b         = blk / (COLP * CP);
    const int colpart   = (blk / CP) % COLP;   // 0: global half, 1: local half
    const int chunkpart = blk % CP;
    const int tid       = threadIdx.x;
    const int fc        = colpart * 128 + tid; // float4-column in [0, 256)

    __shared__ int s_cnt[64];
    __shared__ float s_inv;

    if (colpart == 1) {
        if (tid < 64) s_cnt[tid] = g_counts[b * SS + tid];
        __syncthreads();
        if (tid < 16) s_cnt[tid] += s_cnt[tid + 16] + s_cnt[tid + 32] + s_cnt[tid + 48];
        __syncthreads();
        if (tid == 0) {
            int tot = 0;
            #pragma unroll
            for (int i = 0; i < 16; ++i) tot += s_cnt[i];
            s_inv = 1.0f / (float)(tot > 1 ? tot : 1);
        }
        __syncthreads();
    } else {
        const int L = lengths[b];
        if (tid == 0) s_inv = 1.0f / (float)(L > 1 ? L : 1);
        __syncthreads();
    }
    const float inv = s_inv;

    const int c0 = chunkpart * (SS / CP);
    const float4* p = reinterpret_cast<const float4*>(g_partial)
                    + ((size_t)b * SS + c0) * (2 * HH / 4) + fc;

    float4 acc = make_float4(0.f, 0.f, 0.f, 0.f);
    #pragma unroll
    for (int c = 0; c < SS / CP; ++c) {
        float4 v = p[(size_t)c * (2 * HH / 4)];
        acc.x += v.x; acc.y += v.y; acc.z += v.z; acc.w += v.w;
    }

    float* o = out + (size_t)b * 2 * HH + 4 * fc;
    atomicAdd(&o[0], acc.x * inv);
    atomicAdd(&o[1], acc.y * inv);
    atomicAdd(&o[2], acc.z * inv);
    atomicAdd(&o[3], acc.w * inv);
}

extern "C" void kernel_launch(void* const* d_in, const int* in_sizes, int n_in,
                              void* d_out, int out_size)
{
    const float4* x       = (const float4*)d_in[0];   // [B,T,H] f32
    const int*    lengths = (const int*)d_in[1];      // [B] i32
    const int*    mask    = (const int*)d_in[2];      // [B,T] bool -> i32
    float*        out     = (float*)d_out;            // [B, 2H] f32

    pass1_kernel<<<BB * SS, 128>>>(x, lengths, mask, (float4*)out);
    pass2_kernel<<<BB * COLP * CP, 128>>>(lengths, out);
}